// round 15
// baseline (speedup 1.0000x reference)
#include <cuda_runtime.h>
#include <cuda_bf16.h>

#define BQ 256
#define DD 256
#define NBANK 100000
#define TN 128
#define NUM_TILES ((NBANK + TN - 1) / TN)      // 782
#define NCH 8
#define KCH 32
#define SR 80                                   // smem row stride (64B data + 16B pad)
#define THREADS 512
#define NSPLIT 8
#define TILES_PER_SPLIT ((NUM_TILES + NSPLIT - 1) / NSPLIT)   // 98

typedef unsigned long long ull;
typedef unsigned int u32;

// --------------- device scratch --------------------------------------------
__device__ ull    g_aP[BQ];
__device__ ull    g_aF[BQ];
__device__ ull    g_ex[BQ];
__device__ float  g_a2[BQ];
__device__ int    g_b2maxI;
__device__ uint4  g_Q[NCH][BQ][4];              // hi-split queries (L2-resident)
__device__ float  g_b2[NBANK];
__device__ ull    g_tileP[(size_t)BQ * NUM_TILES];   // [q][tile]
__device__ ull    g_tileF[(size_t)BQ * NUM_TILES];

// --------------- smem layout -------------------------------------------------
#define QBUF  (BQ * SR)                     // 20480
#define BBUF  (TN * SR)                     // 10240
#define OFF_Q    0                          // [2 buf][256][SR]
#define OFF_B    (2 * QBUF)                 // 40960: [2 buf][128][SR]
#define OFF_RED  (OFF_B + 2 * BBUF)         // 61440
#define OFF_B2S  (OFF_RED + 2 * BQ * 8)     // 65536
#define OFF_SCLU (OFF_B2S + 512)
#define OFF_SCLS (OFF_SCLU + 512)
#define OFF_SCID (OFF_SCLS + 512)
#define OFF_SGT  (OFF_SCID + 1024)
#define SMEM_TOTAL (OFF_SGT + 1024)         // 69120

// --------------- helpers -----------------------------------------------------
__device__ __forceinline__ u32 smem_u32(const void* p) {
    u32 a;
    asm("{ .reg .u64 t; cvta.to.shared.u64 t, %1; cvt.u32.u64 %0, t; }" : "=r"(a) : "l"(p));
    return a;
}
#define LDSM_X4(r, addr) \
    asm volatile("ldmatrix.sync.aligned.m8n8.x4.shared.b16 {%0,%1,%2,%3}, [%4];" \
        : "=r"((r)[0]), "=r"((r)[1]), "=r"((r)[2]), "=r"((r)[3]) : "r"(addr))
#define MMA16816(d, a, b0, b1) \
    asm volatile("mma.sync.aligned.m16n8k16.row.col.f32.bf16.bf16.f32 " \
        "{%0,%1,%2,%3}, {%4,%5,%6,%7}, {%8,%9}, {%0,%1,%2,%3};" \
        : "+f"((d)[0]), "+f"((d)[1]), "+f"((d)[2]), "+f"((d)[3]) \
        : "r"((a)[0]), "r"((a)[1]), "r"((a)[2]), "r"((a)[3]), "r"(b0), "r"(b1))
#define CP_ASYNC16(dst, src) \
    asm volatile("cp.async.cg.shared.global [%0], [%1], 16;" :: "r"(dst), "l"(src) : "memory")
#define CP_COMMIT() asm volatile("cp.async.commit_group;" ::: "memory")
#define CP_WAIT0()  asm volatile("cp.async.wait_group 0;" ::: "memory")

__device__ __forceinline__ ull encode(float f, int n) {
    u32 u = __float_as_uint(f);
    u = (u & 0x80000000u) ? ~u : (u | 0x80000000u);
    return ((ull)u << 32) | (u32)n;
}
__device__ __forceinline__ float decode_hi(ull e) {
    u32 u = (u32)(e >> 32);
    u = (u & 0x80000000u) ? (u ^ 0x80000000u) : ~u;
    return __uint_as_float(u);
}
__device__ __forceinline__ u32 hi2(float a0, float a1) {
    __nv_bfloat16 h0 = __float2bfloat16(a0);
    __nv_bfloat16 h1 = __float2bfloat16(a1);
    return (u32)__bfloat16_as_ushort(h0) | ((u32)__bfloat16_as_ushort(h1) << 16);
}

// ---------------------------------------------------------------------------
// prep: one block per query, 128 threads.
// ---------------------------------------------------------------------------
__global__ void __launch_bounds__(128) prep_kernel(const float* __restrict__ feat) {
    const int q = blockIdx.x, t = threadIdx.x;
    const float2 v = ((const float2*)(feat + (size_t)q * DD))[t];
    ((u32*)g_Q)[(t >> 4) * (BQ * 16) + q * 16 + (t & 15)] = hi2(v.x, v.y);

    float s = fmaf(v.x, v.x, v.y * v.y);
#pragma unroll
    for (int o = 16; o; o >>= 1) s += __shfl_xor_sync(0xffffffffu, s, o);
    __shared__ float ws[4];
    if ((t & 31) == 0) ws[t >> 5] = s;
    __syncthreads();
    if (t == 0) {
        g_a2[q] = ws[0] + ws[1] + ws[2] + ws[3];
        g_aP[q] = ~0ULL;
        g_aF[q] = ~0ULL;
        g_ex[q] = ~0ULL;
        if (q == 0) g_b2maxI = 0;
    }
}

// ---------------------------------------------------------------------------
__device__ __forceinline__ void stage_q(u32 smb, int buf, int c, int tid) {
#pragma unroll
    for (int p = 0; p < 2; ++p) {
        int idx = tid + THREADS * p;
        int row = idx >> 2, seg = idx & 3;
        CP_ASYNC16(smb + OFF_Q + (u32)buf * QBUF + (u32)row * SR + (u32)seg * 16,
                   &g_Q[c][row][seg]);
    }
}

__device__ __forceinline__ void ldB(const float* __restrict__ bank, int gn, int c,
                                    int quarter, float4* r) {
    if (gn < NBANK) {
        const float4* p = (const float4*)(bank + (size_t)gn * DD + c * KCH + quarter * 8);
        r[0] = p[0]; r[1] = p[1];
    } else {
        r[0] = r[1] = make_float4(0.f, 0.f, 0.f, 0.f);
    }
}
__device__ __forceinline__ float cvtB(const float4* r, char* dst) {
    float s = 0.f;
#pragma unroll
    for (int i = 0; i < 2; ++i) {
        s = fmaf(r[i].x, r[i].x, s); s = fmaf(r[i].y, r[i].y, s);
        s = fmaf(r[i].z, r[i].z, s); s = fmaf(r[i].w, r[i].w, s);
    }
    *(uint4*)dst = make_uint4(hi2(r[0].x, r[0].y), hi2(r[0].z, r[0].w),
                              hi2(r[1].x, r[1].y), hi2(r[1].z, r[1].w));
    return s;
}

// ---------------------------------------------------------------------------
// Phase A: 512 threads (16 warps), warp tile 32q x 64n; fused streaming
// convert + hi-only bf16 HMMA GEMM + masked dual argmin. (Unchanged R14.)
// ---------------------------------------------------------------------------
__global__ void __launch_bounds__(THREADS, 1) main_kernel(
    const float* __restrict__ bank,
    const int* __restrict__ cluL, const int* __restrict__ clsL,
    const int* __restrict__ cid,  const int* __restrict__ gt)
{
    extern __shared__ char sm[];
    const u32 smb  = smem_u32(sm);
    const int tid  = threadIdx.x;
    const int lane = tid & 31;
    const int w    = tid >> 5;
    const int n0   = blockIdx.x * TN;

    ull*   redP = (ull*)(sm + OFF_RED);
    ull*   redF = redP + BQ;
    float* b2s  = (float*)(sm + OFF_B2S);
    int*   sClu = (int*)(sm + OFF_SCLU);
    int*   sCls = (int*)(sm + OFF_SCLS);
    int*   sCid = (int*)(sm + OFF_SCID);
    int*   sGt  = (int*)(sm + OFF_SGT);

    const int crow = tid >> 2;
    const int cq   = tid & 3;
    const int cgn  = n0 + crow;
    float b2part = 0.f;

    stage_q(smb, 0, 0, tid);
    CP_COMMIT();
    {
        float4 r[2];
        ldB(bank, cgn, 0, cq, r);
        b2part += cvtB(r, sm + OFF_B + crow * SR + cq * 16);
    }

    if (tid < BQ) {
        redP[tid] = ~0ULL;
        redF[tid] = ~0ULL;
        sCid[tid] = cid[tid];
        sGt[tid]  = gt[tid];
    }
    if (tid < TN) {
        int n = n0 + tid;
        bool v = (n < NBANK);
        sClu[tid] = v ? cluL[n] : -1;
        sCls[tid] = v ? clsL[n] : 0x7fffffff;
    }

    const int q0 = (w & 7) * 32;
    const int nh = (w >> 3) * 64;

    float acc[2][8][4];
#pragma unroll
    for (int mi = 0; mi < 2; mi++)
#pragma unroll
        for (int nt = 0; nt < 8; nt++)
#pragma unroll
            for (int r = 0; r < 4; r++) acc[mi][nt][r] = 0.f;

    const u32 aRowOff = (u32)(q0 + (lane & 15)) * SR + (u32)(lane >> 4) * 16;
    const int bRow    = nh + ((lane >> 4) & 1) * 8 + (lane & 7);
    const u32 bColB   = ((lane >> 3) & 1) * 16;

    CP_WAIT0();
    __syncthreads();

#pragma unroll 1
    for (int c = 0; c < NCH; ++c) {
        float4 pre[2];
        if (c + 1 < NCH) {
            ldB(bank, cgn, c + 1, cq, pre);
            stage_q(smb, (c + 1) & 1, c + 1, tid);
            CP_COMMIT();
        }

        const u32 qH  = smb + OFF_Q + (u32)(c & 1) * QBUF + aRowOff;
        const u32 bB0 = smb + OFF_B + (u32)(c & 1) * BBUF;
#pragma unroll
        for (int kk = 0; kk < KCH; kk += 16) {
            const u32 kb = (u32)kk * 2 + bColB;
            u32 aH[2][4];
#pragma unroll
            for (int mi = 0; mi < 2; mi++) LDSM_X4(aH[mi], qH + mi * 16 * SR + kk * 2);
            u32 bB[16];
#pragma unroll
            for (int p = 0; p < 4; p++)
                LDSM_X4(&bB[4 * p], bB0 + (u32)(bRow + p * 16) * SR + kb);
#pragma unroll
            for (int mi = 0; mi < 2; mi++)
#pragma unroll
                for (int nt = 0; nt < 8; nt++)
                    MMA16816(acc[mi][nt], aH[mi], bB[2 * nt], bB[2 * nt + 1]);
        }

        if (c + 1 < NCH)
            b2part += cvtB(pre, sm + OFF_B + ((c + 1) & 1) * BBUF + crow * SR + cq * 16);

        CP_WAIT0();
        __syncthreads();
    }

    {
        b2part += __shfl_xor_sync(0xffffffffu, b2part, 1);
        b2part += __shfl_xor_sync(0xffffffffu, b2part, 2);
        if (cq == 0) {
            b2s[crow] = b2part;
            if (cgn < NBANK) {
                g_b2[cgn] = b2part;
                atomicMax(&g_b2maxI, __float_as_int(b2part));
            }
        }
    }
    __syncthreads();

    // ---- epilogue: masked dual argmin from HMMA fragments ----
    {
        const int jb = nh + 2 * (lane & 3);
        float b2r[16]; int clsr[16], clur[16]; bool val[16];
#pragma unroll
        for (int ni = 0; ni < 8; ni++)
#pragma unroll
            for (int h = 0; h < 2; h++) {
                int j = jb + 8 * ni + h, x = ni * 2 + h;
                b2r[x]  = b2s[j];
                clsr[x] = sCls[j];
                clur[x] = sClu[j];
                val[x]  = (n0 + j) < NBANK;
            }
#pragma unroll
        for (int mi = 0; mi < 2; mi++) {
#pragma unroll
            for (int half = 0; half < 2; half++) {
                int r = q0 + mi * 16 + (lane >> 2) + 8 * half;
                int gtq = sGt[r], ciq = sCid[r];
                ull bp = ~0ULL, bf = ~0ULL;
#pragma unroll
                for (int ni = 0; ni < 8; ni++)
#pragma unroll
                    for (int h = 0; h < 2; h++) {
                        int x = ni * 2 + h;
                        if (!val[x] || clsr[x] == gtq) continue;
                        float score = fmaf(-2.f, acc[mi][ni][half * 2 + h], b2r[x]);
                        ull e = encode(score, n0 + jb + 8 * ni + h);
                        if (e < bf) bf = e;
                        if (clur[x] == ciq && e < bp) bp = e;
                    }
#pragma unroll
                for (int o = 1; o <= 2; o <<= 1) {
                    ull tp = __shfl_xor_sync(0xffffffffu, bp, o);
                    ull tf = __shfl_xor_sync(0xffffffffu, bf, o);
                    if (tp < bp) bp = tp;
                    if (tf < bf) bf = tf;
                }
                if ((lane & 3) == 0) {
                    if (bp != ~0ULL) atomicMin(&redP[r], bp);
                    if (bf != ~0ULL) atomicMin(&redF[r], bf);
                }
            }
        }
    }
    __syncthreads();
    if (tid < BQ) {
        ull p = redP[tid], f = redF[tid];
        g_tileP[(size_t)tid * NUM_TILES + blockIdx.x] = p;
        g_tileF[(size_t)tid * NUM_TILES + blockIdx.x] = f;
        if (p != ~0ULL) atomicMin(&g_aP[tid], p);
        if (f != ~0ULL) atomicMin(&g_aF[tid], f);
    }
}

// ---------------------------------------------------------------------------
// Phase B: grid (BQ, NSPLIT); block (q, s) scans its tile slice, rescores
// qualifying rows exactly in fp32, atomicMin into g_ex[q].
// ---------------------------------------------------------------------------
__global__ void __launch_bounds__(256) rescore_kernel(
    const float* __restrict__ feat, const float* __restrict__ bank,
    const int* __restrict__ cluL, const int* __restrict__ clsL,
    const int* __restrict__ cid,  const int* __restrict__ gt)
{
    __shared__ int   s_tiles[TILES_PER_SPLIT];
    __shared__ int   s_cnt;
    __shared__ ull   s_best;
    __shared__ float s_thr;
    __shared__ int   s_hasP, s_gt, s_cid;

    const int q    = blockIdx.x;
    const int t0   = blockIdx.y * TILES_PER_SPLIT;
    const int t1   = min(t0 + TILES_PER_SPLIT, NUM_TILES);
    const int tid  = threadIdx.x;
    const int lane = tid & 31;
    const int w    = tid >> 5;

    if (tid == 0) {
        s_cnt  = 0;
        s_best = ~0ULL;
        bool hasP = (g_aP[q] != ~0ULL);
        float amin = hasP ? decode_hi(g_aP[q]) : decode_hi(g_aF[q]);
        float m = 0.0078125f * 1.05f * sqrtf(g_a2[q] * __int_as_float(g_b2maxI)) + 0.02f;
        s_thr  = amin + 2.f * m;
        s_hasP = hasP ? 1 : 0;
        s_gt   = gt[q];
        s_cid  = cid[q];
    }
    __syncthreads();

    {
        const ull* tmins = (s_hasP ? g_tileP : g_tileF) + (size_t)q * NUM_TILES;
        for (int t = t0 + tid; t < t1; t += 256) {
            ull tm = tmins[t];
            if (tm != ~0ULL && decode_hi(tm) <= s_thr) {
                int i = atomicAdd(&s_cnt, 1);
                s_tiles[i] = t;
            }
        }
    }
    __syncthreads();

    const int cnt = s_cnt;
    if (cnt > 0) {
        const float4* fa = (const float4*)(feat + (size_t)q * DD);
        const float4 qa0 = fa[lane * 2], qa1 = fa[lane * 2 + 1];

        for (int i = 0; i < cnt; ++i) {
            const int n0 = s_tiles[i] * TN;
#pragma unroll 1
            for (int r = w; r < TN; r += 8) {            // warp per row, 8 warps
                int n = n0 + r;
                if (n >= NBANK) continue;
                if (clsL[n] == s_gt) continue;
                if (s_hasP && cluL[n] != s_cid) continue;
                const float4* fb = (const float4*)(bank + (size_t)n * DD);
                float4 b0 = fb[lane * 2], b1 = fb[lane * 2 + 1];
                float d = 0.f;
                d = fmaf(qa0.x, b0.x, d); d = fmaf(qa0.y, b0.y, d);
                d = fmaf(qa0.z, b0.z, d); d = fmaf(qa0.w, b0.w, d);
                d = fmaf(qa1.x, b1.x, d); d = fmaf(qa1.y, b1.y, d);
                d = fmaf(qa1.z, b1.z, d); d = fmaf(qa1.w, b1.w, d);
#pragma unroll
                for (int o = 16; o; o >>= 1) d += __shfl_xor_sync(0xffffffffu, d, o);
                if (lane == 0)
                    atomicMin(&s_best, encode(fmaf(-2.f, d, g_b2[n]), n));
            }
        }
        __syncthreads();
        if (tid == 0 && s_best != ~0ULL) atomicMin(&g_ex[q], s_best);
    }
}

// ---------------------------------------------------------------------------
__global__ void gather_kernel(const float* __restrict__ bank, float* __restrict__ out) {
    int b = blockIdx.x;
    ull e = g_ex[b];
    int idx = (e == ~0ULL) ? 0 : (int)(u32)(e & 0xffffffffu);
    const float4* src = (const float4*)(bank + (size_t)idx * DD);
    float4*       dst = (float4*)(out + (size_t)b * DD);
    dst[threadIdx.x] = src[threadIdx.x];
}

// ---------------------------------------------------------------------------
extern "C" void kernel_launch(void* const* d_in, const int* in_sizes, int n_in,
                              void* d_out, int out_size) {
    const float* feature = (const float*)d_in[0];
    const float* bank    = (const float*)d_in[1];
    const int*   cluL    = (const int*)d_in[2];
    const int*   clsL    = (const int*)d_in[3];
    const int*   cid     = (const int*)d_in[4];
    const int*   gtl     = (const int*)d_in[5];

    cudaFuncSetAttribute(main_kernel,
                         cudaFuncAttributeMaxDynamicSharedMemorySize, SMEM_TOTAL);

    prep_kernel<<<BQ, 128>>>(feature);                                           // #1
    main_kernel<<<NUM_TILES, THREADS, SMEM_TOTAL>>>(bank, cluL, clsL, cid, gtl); // #2
    dim3 rg(BQ, NSPLIT);
    rescore_kernel<<<rg, 256>>>(feature, bank, cluL, clsL, cid, gtl);            // #3
    gather_kernel<<<BQ, 64>>>(bank, (float*)d_out);                              // #4
}